// round 10
// baseline (speedup 1.0000x reference)
#include <cuda_runtime.h>
#include <cuda_bf16.h>

// Erosion (min filter) k=18, SAME (pad_lo=8, pad_hi=9), on y = x*0.5+0.5.
// NCHW (32,3,512,512) fp32 = 96 planes of 512x512.
//
// Vertical-FIRST fused separable min filter, occupancy-tuned:
//  TY=16, smem 32KB, regs capped at 32 -> 4 blocks/SM = 2048 threads (100%).
//  Phase V: thread-per-column, 33 coalesced LDG.32, exact-once 2-segment
//    van Herk (S0[16] only -> small register footprint), 16 vmin rows -> smem.
//    Interior blocks (30/32) take an unguarded pointer-walk path.
//  Phase H: warp-per-row (16 rows): lane owns 4 contiguous cols,
//    conflict-free LDS.128, 18-wide window via 10 wrap-shuffles per 128-col
//    round, fused 0.5x+0.5, coalesced STG.128. One barrier.

#define W 512
#define H 512
#define TY 16
#define NTHREADS 512
#define SMEM_BYTES (TY * W * 4)    // 32,768 B

// Vertical min-18 for one column: taps t[i]=x[g0+i], i=0..32 (exact-once),
// out[o]=min(t[o..o+17]) for o=0..15 -> s_col[o*W].
template <bool GUARD>
__device__ __forceinline__ void vcol_min18(const float* __restrict__ gp,
                                           int g0, float* __restrict__ s_col) {
    const float INF = __int_as_float(0x7f800000);
    const float* p = gp + (long)g0 * W;

    // segment 1: suffix over taps 0..17 -> S0[i] = min(t[i..17]), i<=15
    float S0[16];
    {
        float s;
        if (GUARD) {
            int gr = g0 + 17;
            s = ((unsigned)gr < (unsigned)H) ? p[17 * W] : INF;
        } else {
            s = p[17 * W];
        }
        #pragma unroll
        for (int i = 16; i >= 0; --i) {
            float v;
            if (GUARD) {
                int gr = g0 + i;
                v = ((unsigned)gr < (unsigned)H) ? p[i * W] : INF;
            } else {
                v = p[i * W];
            }
            s = fminf(s, v);
            if (i <= 15) S0[i] = s;
        }
    }
    s_col[0] = S0[0];

    // segment 2: taps 18..32, running prefix, emit out[1..15]
    {
        float pr = INF;
        #pragma unroll
        for (int o = 1; o <= 15; ++o) {
            float v;
            if (GUARD) {
                int gr = g0 + 17 + o;
                v = ((unsigned)gr < (unsigned)H) ? p[(17 + o) * W] : INF;
            } else {
                v = p[(17 + o) * W];
            }
            pr = fminf(pr, v);
            s_col[o * W] = fminf(S0[o], pr);
        }
    }
}

__global__ __launch_bounds__(NTHREADS, 4)
void erode18_kernel(const float* __restrict__ x, float* __restrict__ out) {
    extern __shared__ float s_v[];  // [TY][W] vertical-min tile

    const int tid  = threadIdx.x;
    const int lane = tid & 31;
    const int warp = tid >> 5;
    const int rowBase = blockIdx.x * TY;
    const long plane = (long)blockIdx.y * (W * H);
    const float INF = __int_as_float(0x7f800000);
    const unsigned FULL = 0xFFFFFFFFu;

    // ========== Phase V: vertical min-18, thread-per-column, exact-once ==========
    {
        const float* gp = x + plane + tid;
        const int g0 = rowBase - 8;
        if (g0 >= 0 && g0 + 32 < H)
            vcol_min18<false>(gp, g0, s_v + tid);
        else
            vcol_min18<true>(gp, g0, s_v + tid);
    }
    __syncthreads();

    // ========== Phase H: horizontal min-18, warp-per-row (16 rows) ==========
    {
        const int r = warp;
        const float4* srow = (const float4*)(s_v + r * W);
        float4* orow = (float4*)(out + plane + (long)(rowBase + r) * W);

        float4 v = srow[lane];
        float pS1 = INF, pS2 = INF, pS3 = INF, pF = INF;

        #pragma unroll
        for (int j = 0; j < 4; ++j) {
            float4 vn = (j < 3) ? srow[32 * (j + 1) + lane]
                                : make_float4(INF, INF, INF, INF);
            float P1 = fminf(v.x, v.y);
            float P2 = fminf(P1, v.z);
            float F  = fminf(P2, v.w);
            float S2 = fminf(v.z, v.w);
            float S1 = fminf(v.y, S2);
            float Pn1 = fminf(vn.x, vn.y);
            float Pn2 = fminf(Pn1, vn.z);
            float Fn  = fminf(Pn2, vn.w);

            // src = lane-2 (wrap); wrap sources 30,31 export prev-round values
            float eS0 = (lane >= 30) ? pF  : F;    // pS0 == pF
            float eS1 = (lane >= 30) ? pS1 : S1;
            float eS2 = (lane >= 30) ? pS2 : S2;
            float eS3 = (lane >= 30) ? pS3 : v.w;
            float u0 = __shfl_sync(FULL, eS0, (lane + 30) & 31);
            float u1 = __shfl_sync(FULL, eS1, (lane + 30) & 31);
            float u2 = __shfl_sync(FULL, eS2, (lane + 30) & 31);
            float u3 = __shfl_sync(FULL, eS3, (lane + 30) & 31);
            float eFu = (lane == 31) ? pF : F;
            float fu = __shfl_sync(FULL, eFu, (lane + 31) & 31);
            float eFd = (lane == 0) ? Fn : F;
            float fd = __shfl_sync(FULL, eFd, (lane + 1) & 31);
            float eP1 = (lane <= 1) ? Pn1 : P1;
            float eP2 = (lane <= 1) ? Pn2 : P2;
            float eP3 = (lane <= 1) ? Fn  : F;
            float d1 = __shfl_sync(FULL, eP1, (lane + 2) & 31);
            float d2 = __shfl_sync(FULL, eP2, (lane + 2) & 31);
            float d3 = __shfl_sync(FULL, eP3, (lane + 2) & 31);
            float evx = (lane <= 2) ? vn.x : v.x;
            float dx = __shfl_sync(FULL, evx, (lane + 3) & 31);

            float core = fminf(fminf(fu, F), fd);
            float4 ov;
            ov.x = fmaf(fminf(fminf(u0, core), d1), 0.5f, 0.5f);
            ov.y = fmaf(fminf(fminf(u1, core), d2), 0.5f, 0.5f);
            ov.z = fmaf(fminf(fminf(u2, core), d3), 0.5f, 0.5f);
            ov.w = fmaf(fminf(fminf(u3, core), fminf(d3, dx)), 0.5f, 0.5f);
            orow[32 * j + lane] = ov;

            pS1 = S1; pS2 = S2; pS3 = v.w; pF = F;
            v = vn;
        }
    }
}

extern "C" void kernel_launch(void* const* d_in, const int* in_sizes, int n_in,
                              void* d_out, int out_size) {
    const float* x = (const float*)d_in[0];
    float* out = (float*)d_out;

    // Idempotent host-side attribute set; not part of graph capture.
    cudaFuncSetAttribute(erode18_kernel,
                         cudaFuncAttributeMaxDynamicSharedMemorySize, SMEM_BYTES);

    dim3 grid(H / TY, 96);   // 32 x 96 = 3072 blocks
    erode18_kernel<<<grid, NTHREADS, SMEM_BYTES>>>(x, out);
}

// round 11
// speedup vs baseline: 1.0399x; 1.0399x over previous
#include <cuda_runtime.h>
#include <cuda_bf16.h>

// Erosion (min filter) k=18, SAME (pad_lo=8, pad_hi=9), on y = x*0.5+0.5.
// NCHW (32,3,512,512) fp32 = 96 planes of 512x512.
//
// R9 skeleton (best: 36.5us) + __stcs streaming output stores:
//  Output (write-once) no longer evicts the input from L2 between graph
//  replays -> input stays L2-resident -> DRAM read traffic ~0, total DRAM
//  bytes ~154MB -> ~105MB. Everything else identical to R9.
//  Phase V: thread-per-column, 49 LDG.32, exact-once 3-segment van Herk,
//    32 vmin rows -> smem; interior blocks unguarded.
//  Phase H: warp-per-row, 10 wrap-shuffles per 128-col round, STG.128.cs.
//  smem 64KB, 3 blocks/SM, one barrier.

#define W 512
#define H 512
#define TY 32
#define NTHREADS 512
#define SMEM_BYTES (TY * W * 4)    // 65,536 B

template <bool GUARD>
__device__ __forceinline__ void vcol_min18(const float* __restrict__ gp,
                                           int g0, float* __restrict__ s_col) {
    const float INF = __int_as_float(0x7f800000);
    const float* p = gp + (long)g0 * W;

    // segment 1: suffix over taps 0..17 -> S0[i] = min(t[i..17])
    float S0[18];
    {
        float s;
        if (GUARD) {
            int gr = g0 + 17;
            s = ((unsigned)gr < (unsigned)H) ? p[17 * W] : INF;
        } else {
            s = p[17 * W];
        }
        S0[17] = s;
        #pragma unroll
        for (int i = 16; i >= 0; --i) {
            float v;
            if (GUARD) {
                int gr = g0 + i;
                v = ((unsigned)gr < (unsigned)H) ? p[i * W] : INF;
            } else {
                v = p[i * W];
            }
            s = fminf(s, v);
            S0[i] = s;
        }
    }
    s_col[0] = S0[0];

    // segment 2: taps 18..35 -> t1, prefix-emit vmin[1..18]
    float t1[18];
    {
        float pr = INF;
        #pragma unroll
        for (int i = 0; i <= 17; ++i) {
            float v;
            if (GUARD) {
                int gr = g0 + 18 + i;
                v = ((unsigned)gr < (unsigned)H) ? p[(18 + i) * W] : INF;
            } else {
                v = p[(18 + i) * W];
            }
            t1[i] = v;
            pr = fminf(pr, v);
            float o = (i <= 16) ? fminf(S0[i + 1], pr) : pr;
            s_col[(i + 1) * W] = o;
        }
    }

    // suffix over t1 in place: t1[i] = min(t1[i..17])
    #pragma unroll
    for (int i = 16; i >= 0; --i) t1[i] = fminf(t1[i], t1[i + 1]);

    // segment 3: taps 36..48, prefix-emit vmin[19..31]
    {
        float q = INF;
        #pragma unroll
        for (int i = 0; i <= 12; ++i) {
            float v;
            if (GUARD) {
                int gr = g0 + 36 + i;
                v = ((unsigned)gr < (unsigned)H) ? p[(36 + i) * W] : INF;
            } else {
                v = p[(36 + i) * W];
            }
            q = fminf(q, v);
            s_col[(19 + i) * W] = fminf(t1[i + 1], q);
        }
    }
}

__global__ __launch_bounds__(NTHREADS, 3)
void erode18_kernel(const float* __restrict__ x, float* __restrict__ out) {
    extern __shared__ float s_v[];  // [TY][W] vertical-min tile

    const int tid  = threadIdx.x;
    const int lane = tid & 31;
    const int warp = tid >> 5;
    const int rowBase = blockIdx.x * TY;
    const long plane = (long)blockIdx.y * (W * H);
    const float INF = __int_as_float(0x7f800000);
    const unsigned FULL = 0xFFFFFFFFu;

    // ========== Phase V: vertical min-18, thread-per-column, exact-once ==========
    {
        const float* gp = x + plane + tid;
        const int g0 = rowBase - 8;
        if (g0 >= 0 && g0 + 48 < H)
            vcol_min18<false>(gp, g0, s_v + tid);
        else
            vcol_min18<true>(gp, g0, s_v + tid);
    }
    __syncthreads();

    // ========== Phase H: horizontal min-18, warp-per-row (32 rows) ==========
    #pragma unroll
    for (int rr = 0; rr < 2; ++rr) {
        const int r = warp + rr * 16;
        const float4* srow = (const float4*)(s_v + r * W);
        float4* orow = (float4*)(out + plane + (long)(rowBase + r) * W);

        float4 v = srow[lane];
        float pS1 = INF, pS2 = INF, pS3 = INF, pF = INF;

        #pragma unroll
        for (int j = 0; j < 4; ++j) {
            float4 vn = (j < 3) ? srow[32 * (j + 1) + lane]
                                : make_float4(INF, INF, INF, INF);
            float P1 = fminf(v.x, v.y);
            float P2 = fminf(P1, v.z);
            float F  = fminf(P2, v.w);
            float S2 = fminf(v.z, v.w);
            float S1 = fminf(v.y, S2);
            float Pn1 = fminf(vn.x, vn.y);
            float Pn2 = fminf(Pn1, vn.z);
            float Fn  = fminf(Pn2, vn.w);

            // src = lane-2 (wrap); wrap sources 30,31 export prev-round values
            float eS0 = (lane >= 30) ? pF  : F;    // pS0 == pF
            float eS1 = (lane >= 30) ? pS1 : S1;
            float eS2 = (lane >= 30) ? pS2 : S2;
            float eS3 = (lane >= 30) ? pS3 : v.w;
            float u0 = __shfl_sync(FULL, eS0, (lane + 30) & 31);
            float u1 = __shfl_sync(FULL, eS1, (lane + 30) & 31);
            float u2 = __shfl_sync(FULL, eS2, (lane + 30) & 31);
            float u3 = __shfl_sync(FULL, eS3, (lane + 30) & 31);
            float eFu = (lane == 31) ? pF : F;
            float fu = __shfl_sync(FULL, eFu, (lane + 31) & 31);
            float eFd = (lane == 0) ? Fn : F;
            float fd = __shfl_sync(FULL, eFd, (lane + 1) & 31);
            float eP1 = (lane <= 1) ? Pn1 : P1;
            float eP2 = (lane <= 1) ? Pn2 : P2;
            float eP3 = (lane <= 1) ? Fn  : F;
            float d1 = __shfl_sync(FULL, eP1, (lane + 2) & 31);
            float d2 = __shfl_sync(FULL, eP2, (lane + 2) & 31);
            float d3 = __shfl_sync(FULL, eP3, (lane + 2) & 31);
            float evx = (lane <= 2) ? vn.x : v.x;
            float dx = __shfl_sync(FULL, evx, (lane + 3) & 31);

            float core = fminf(fminf(fu, F), fd);
            float4 ov;
            ov.x = fmaf(fminf(fminf(u0, core), d1), 0.5f, 0.5f);
            ov.y = fmaf(fminf(fminf(u1, core), d2), 0.5f, 0.5f);
            ov.z = fmaf(fminf(fminf(u2, core), d3), 0.5f, 0.5f);
            ov.w = fmaf(fminf(fminf(u3, core), fminf(d3, dx)), 0.5f, 0.5f);
            __stcs(&orow[32 * j + lane], ov);   // streaming store: keep L2 for input

            pS1 = S1; pS2 = S2; pS3 = v.w; pF = F;
            v = vn;
        }
    }
}

extern "C" void kernel_launch(void* const* d_in, const int* in_sizes, int n_in,
                              void* d_out, int out_size) {
    const float* x = (const float*)d_in[0];
    float* out = (float*)d_out;

    // Idempotent host-side attribute set; not part of graph capture.
    cudaFuncSetAttribute(erode18_kernel,
                         cudaFuncAttributeMaxDynamicSharedMemorySize, SMEM_BYTES);

    dim3 grid(H / TY, 96);   // 16 x 96 = 1536 blocks
    erode18_kernel<<<grid, NTHREADS, SMEM_BYTES>>>(x, out);
}

// round 12
// speedup vs baseline: 1.0471x; 1.0069x over previous
#include <cuda_runtime.h>
#include <cuda_bf16.h>

// Erosion (min filter) k=18, SAME (pad_lo=8, pad_hi=9), on y = x*0.5+0.5.
// NCHW (32,3,512,512) fp32 = 96 planes of 512x512.
//
// R9 skeleton (best: 36.5us kernel / 41.4us wall) + __ldcg on phase-V input:
//  input lines are single-use per block (halo reuse is cross-SM), so bypass
//  L1 allocation (L2-only). Everything else identical to R9.
//  Phase V: thread-per-column, 49 coalesced LDG.32, exact-once 3-segment
//    van Herk in registers, 32 vmin rows -> smem; interior blocks unguarded.
//  Phase H: warp-per-row, 10 wrap-shuffles per 128-col round, fused
//    0.5x+0.5, coalesced STG.128. smem 64KB, 3 blocks/SM, one barrier.

#define W 512
#define H 512
#define TY 32
#define NTHREADS 512
#define SMEM_BYTES (TY * W * 4)    // 65,536 B

template <bool GUARD>
__device__ __forceinline__ void vcol_min18(const float* __restrict__ gp,
                                           int g0, float* __restrict__ s_col) {
    const float INF = __int_as_float(0x7f800000);
    const float* p = gp + (long)g0 * W;

    // segment 1: suffix over taps 0..17 -> S0[i] = min(t[i..17])
    float S0[18];
    {
        float s;
        if (GUARD) {
            int gr = g0 + 17;
            s = ((unsigned)gr < (unsigned)H) ? __ldcg(p + 17 * W) : INF;
        } else {
            s = __ldcg(p + 17 * W);
        }
        S0[17] = s;
        #pragma unroll
        for (int i = 16; i >= 0; --i) {
            float v;
            if (GUARD) {
                int gr = g0 + i;
                v = ((unsigned)gr < (unsigned)H) ? __ldcg(p + i * W) : INF;
            } else {
                v = __ldcg(p + i * W);
            }
            s = fminf(s, v);
            S0[i] = s;
        }
    }
    s_col[0] = S0[0];

    // segment 2: taps 18..35 -> t1, prefix-emit vmin[1..18]
    float t1[18];
    {
        float pr = INF;
        #pragma unroll
        for (int i = 0; i <= 17; ++i) {
            float v;
            if (GUARD) {
                int gr = g0 + 18 + i;
                v = ((unsigned)gr < (unsigned)H) ? __ldcg(p + (18 + i) * W) : INF;
            } else {
                v = __ldcg(p + (18 + i) * W);
            }
            t1[i] = v;
            pr = fminf(pr, v);
            float o = (i <= 16) ? fminf(S0[i + 1], pr) : pr;
            s_col[(i + 1) * W] = o;
        }
    }

    // suffix over t1 in place: t1[i] = min(t1[i..17])
    #pragma unroll
    for (int i = 16; i >= 0; --i) t1[i] = fminf(t1[i], t1[i + 1]);

    // segment 3: taps 36..48, prefix-emit vmin[19..31]
    {
        float q = INF;
        #pragma unroll
        for (int i = 0; i <= 12; ++i) {
            float v;
            if (GUARD) {
                int gr = g0 + 36 + i;
                v = ((unsigned)gr < (unsigned)H) ? __ldcg(p + (36 + i) * W) : INF;
            } else {
                v = __ldcg(p + (36 + i) * W);
            }
            q = fminf(q, v);
            s_col[(19 + i) * W] = fminf(t1[i + 1], q);
        }
    }
}

__global__ __launch_bounds__(NTHREADS, 3)
void erode18_kernel(const float* __restrict__ x, float* __restrict__ out) {
    extern __shared__ float s_v[];  // [TY][W] vertical-min tile

    const int tid  = threadIdx.x;
    const int lane = tid & 31;
    const int warp = tid >> 5;
    const int rowBase = blockIdx.x * TY;
    const long plane = (long)blockIdx.y * (W * H);
    const float INF = __int_as_float(0x7f800000);
    const unsigned FULL = 0xFFFFFFFFu;

    // ========== Phase V: vertical min-18, thread-per-column, exact-once ==========
    {
        const float* gp = x + plane + tid;
        const int g0 = rowBase - 8;
        if (g0 >= 0 && g0 + 48 < H)
            vcol_min18<false>(gp, g0, s_v + tid);
        else
            vcol_min18<true>(gp, g0, s_v + tid);
    }
    __syncthreads();

    // ========== Phase H: horizontal min-18, warp-per-row (32 rows) ==========
    #pragma unroll
    for (int rr = 0; rr < 2; ++rr) {
        const int r = warp + rr * 16;
        const float4* srow = (const float4*)(s_v + r * W);
        float4* orow = (float4*)(out + plane + (long)(rowBase + r) * W);

        float4 v = srow[lane];
        float pS1 = INF, pS2 = INF, pS3 = INF, pF = INF;

        #pragma unroll
        for (int j = 0; j < 4; ++j) {
            float4 vn = (j < 3) ? srow[32 * (j + 1) + lane]
                                : make_float4(INF, INF, INF, INF);
            float P1 = fminf(v.x, v.y);
            float P2 = fminf(P1, v.z);
            float F  = fminf(P2, v.w);
            float S2 = fminf(v.z, v.w);
            float S1 = fminf(v.y, S2);
            float Pn1 = fminf(vn.x, vn.y);
            float Pn2 = fminf(Pn1, vn.z);
            float Fn  = fminf(Pn2, vn.w);

            // src = lane-2 (wrap); wrap sources 30,31 export prev-round values
            float eS0 = (lane >= 30) ? pF  : F;    // pS0 == pF
            float eS1 = (lane >= 30) ? pS1 : S1;
            float eS2 = (lane >= 30) ? pS2 : S2;
            float eS3 = (lane >= 30) ? pS3 : v.w;
            float u0 = __shfl_sync(FULL, eS0, (lane + 30) & 31);
            float u1 = __shfl_sync(FULL, eS1, (lane + 30) & 31);
            float u2 = __shfl_sync(FULL, eS2, (lane + 30) & 31);
            float u3 = __shfl_sync(FULL, eS3, (lane + 30) & 31);
            float eFu = (lane == 31) ? pF : F;
            float fu = __shfl_sync(FULL, eFu, (lane + 31) & 31);
            float eFd = (lane == 0) ? Fn : F;
            float fd = __shfl_sync(FULL, eFd, (lane + 1) & 31);
            float eP1 = (lane <= 1) ? Pn1 : P1;
            float eP2 = (lane <= 1) ? Pn2 : P2;
            float eP3 = (lane <= 1) ? Fn  : F;
            float d1 = __shfl_sync(FULL, eP1, (lane + 2) & 31);
            float d2 = __shfl_sync(FULL, eP2, (lane + 2) & 31);
            float d3 = __shfl_sync(FULL, eP3, (lane + 2) & 31);
            float evx = (lane <= 2) ? vn.x : v.x;
            float dx = __shfl_sync(FULL, evx, (lane + 3) & 31);

            float core = fminf(fminf(fu, F), fd);
            float4 ov;
            ov.x = fmaf(fminf(fminf(u0, core), d1), 0.5f, 0.5f);
            ov.y = fmaf(fminf(fminf(u1, core), d2), 0.5f, 0.5f);
            ov.z = fmaf(fminf(fminf(u2, core), d3), 0.5f, 0.5f);
            ov.w = fmaf(fminf(fminf(u3, core), fminf(d3, dx)), 0.5f, 0.5f);
            orow[32 * j + lane] = ov;

            pS1 = S1; pS2 = S2; pS3 = v.w; pF = F;
            v = vn;
        }
    }
}

extern "C" void kernel_launch(void* const* d_in, const int* in_sizes, int n_in,
                              void* d_out, int out_size) {
    const float* x = (const float*)d_in[0];
    float* out = (float*)d_out;

    // Idempotent host-side attribute set; not part of graph capture.
    cudaFuncSetAttribute(erode18_kernel,
                         cudaFuncAttributeMaxDynamicSharedMemorySize, SMEM_BYTES);

    dim3 grid(H / TY, 96);   // 16 x 96 = 1536 blocks
    erode18_kernel<<<grid, NTHREADS, SMEM_BYTES>>>(x, out);
}